// round 2
// baseline (speedup 1.0000x reference)
#include <cuda_runtime.h>
#include <cstdint>

// Problem constants
#define NB   32
#define CH   64          // in channels == out channels
#define HH   112
#define WW   112
#define HWSZ (HH*WW)             // 12544
#define PIX  (NB*HWSZ)           // 401408
#define ELEMS (NB*CH*HWSZ)       // 25690112
#define NW   576                 // 64 oc * 9 taps
#define EPSV 1e-5

// Scratch (device globals only — no allocations allowed)
__device__ unsigned long long g_xbits[PIX];          // 3.2 MB packed activation signs
__device__ unsigned long long g_wbits[NW];           // packed weight signs [o*9+tap]
__device__ unsigned char      g_popcw[NW];           // popc of each weight word
__device__ float              g_scale[CH];           // mean |w| per output channel
__device__ long long          g_S1[CH];              // exact sum of s
__device__ long long          g_S2[CH];              // exact sum of s^2
__device__ float              g_A[CH], g_B[CH];      // folded BN coefficients
__device__ short              g_sint[ELEMS];         // 51 MB conv integer results (NCHW)

// ---------------------------------------------------------------------------
// K0: weight prep. 1 block, 576 threads. Also zeroes the stat accumulators
// (must happen every launch: graph replays reuse the globals).
// ---------------------------------------------------------------------------
__global__ void k0_prep(const float* __restrict__ wflat) {
    int t = threadIdx.x;           // 0..575
    if (t < NW) {
        int o   = t / 9;
        int tap = t % 9;
        unsigned long long bits = 0ull;
        #pragma unroll 8
        for (int i = 0; i < CH; i++) {
            // flat index: ((o*64 + i)*3 + kh)*3 + kw = (o*64+i)*9 + tap
            float w = wflat[(o * CH + i) * 9 + tap];
            bits |= (unsigned long long)(w < 0.0f) << i;
        }
        g_wbits[t] = bits;
        g_popcw[t] = (unsigned char)__popcll(bits);
    }
    if (t < CH) {
        // per-output-channel mean |w| over 576 weights
        float s = 0.0f;
        const float* wp = wflat + t * CH * 9;
        for (int j = 0; j < CH * 9; j++) s += fabsf(wp[j]);
        g_scale[t] = s * (1.0f / (float)(CH * 9));
        g_S1[t] = 0ll;
        g_S2[t] = 0ll;
    }
}

// ---------------------------------------------------------------------------
// K1: pack sign bits of x. One thread per pixel, loops 64 channels.
// Coalesced: consecutive threads -> consecutive w within each channel plane.
// ---------------------------------------------------------------------------
__global__ void k1_pack(const float* __restrict__ x) {
    int p = blockIdx.x * blockDim.x + threadIdx.x;   // pixel id, exact grid
    int n  = p / HWSZ;
    int hw = p % HWSZ;
    const float* xp = x + (size_t)n * CH * HWSZ + hw;
    unsigned long long bits = 0ull;
    #pragma unroll 8
    for (int c = 0; c < CH; c++) {
        float v = xp[(size_t)c * HWSZ];
        bits |= (unsigned long long)(v < 0.0f) << c;
    }
    g_xbits[p] = bits;
}

// ---------------------------------------------------------------------------
// K2: binary conv via xor+popc. One thread per pixel computes all 64 output
// channels; exact integer sums reduced warp->block->global.
// ---------------------------------------------------------------------------
__global__ void __launch_bounds__(256) k2_conv(void) {
    __shared__ unsigned long long ws[NW];
    __shared__ unsigned char     wp[NW];
    __shared__ int bs1[CH], bs2[CH];

    int tid = threadIdx.x;
    for (int j = tid; j < NW; j += 256) { ws[j] = g_wbits[j]; wp[j] = g_popcw[j]; }
    if (tid < CH) { bs1[tid] = 0; bs2[tid] = 0; }
    __syncthreads();

    int p  = blockIdx.x * 256 + tid;                 // 401408 = 1568*256 exact
    int n  = p / HWSZ;
    int hw = p % HWSZ;
    int h  = hw / WW;
    int w  = hw % WW;

    // gather 3x3 neighborhood of packed words; invalid taps -> 0 + mask bit
    unsigned long long xb[9];
    int mask = 0;
    const unsigned long long* xrow = g_xbits + (size_t)n * HWSZ;
    #pragma unroll
    for (int dh = -1; dh <= 1; dh++) {
        #pragma unroll
        for (int dw = -1; dw <= 1; dw++) {
            int t  = (dh + 1) * 3 + (dw + 1);
            int hh = h + dh, ww2 = w + dw;
            bool valid = (hh >= 0) & (hh < HH) & (ww2 >= 0) & (ww2 < WW);
            xb[t] = valid ? xrow[hh * WW + ww2] : 0ull;
            if (!valid) mask |= 1 << t;
        }
    }
    int nv = 9 - __popc(mask);
    size_t obase = (size_t)n * CH * HWSZ + hw;       // + o*HWSZ per channel

    for (int o = 0; o < CH; o++) {
        int acc = 0;
        #pragma unroll
        for (int t = 0; t < 9; t++)
            acc += __popcll(xb[t] ^ ws[o * 9 + t]);
        // border correction: zero words contributed popc(wbits); cancel them
        int corr = 0;
        if (mask) {
            int m = mask;
            while (m) { int t = __ffs(m) - 1; m &= m - 1; corr += wp[o * 9 + t]; }
        }
        int s = 64 * nv - 2 * acc + 2 * corr;
        g_sint[obase + (size_t)o * HWSZ] = (short)s;

        int w1 = __reduce_add_sync(0xffffffffu, s);
        int w2 = __reduce_add_sync(0xffffffffu, s * s);
        if ((tid & 31) == 0) {
            atomicAdd(&bs1[o], w1);
            atomicAdd(&bs2[o], w2);
        }
    }
    __syncthreads();
    if (tid < CH) {
        atomicAdd((unsigned long long*)&g_S1[tid], (unsigned long long)(long long)bs1[tid]);
        atomicAdd((unsigned long long*)&g_S2[tid], (unsigned long long)(long long)bs2[tid]);
    }
}

// ---------------------------------------------------------------------------
// K3: fold BN into per-channel A,B.  out = s*A[o] + B[o] + x
// ---------------------------------------------------------------------------
__global__ void k3_final(const float* __restrict__ gamma, const float* __restrict__ beta) {
    int o = threadIdx.x;
    if (o >= CH) return;
    const double cnt = (double)PIX;
    double sc   = (double)g_scale[o];
    double mean = sc * ((double)g_S1[o] / cnt);
    double ex2  = sc * sc * ((double)g_S2[o] / cnt);
    double var  = ex2 - mean * mean;
    double inv  = (double)gamma[o] * rsqrt(var + EPSV);
    g_A[o] = (float)(sc * inv);
    g_B[o] = (float)((double)beta[o] - mean * inv);
}

// ---------------------------------------------------------------------------
// K4: elementwise  out = s*A + B + x   (vectorized x4; 12544 % 4 == 0 so all
// 4 elements share the same channel)
// ---------------------------------------------------------------------------
__global__ void k4_epilogue(const float* __restrict__ x, float* __restrict__ out) {
    int i = blockIdx.x * blockDim.x + threadIdx.x;   // index in units of 4
    int o = ((i * 4) / HWSZ) & (CH - 1);
    float a = g_A[o], b = g_B[o];
    float4 xv = ((const float4*)x)[i];
    short4 sv = ((const short4*)g_sint)[i];
    float4 r;
    r.x = (float)sv.x * a + b + xv.x;
    r.y = (float)sv.y * a + b + xv.y;
    r.z = (float)sv.z * a + b + xv.z;
    r.w = (float)sv.w * a + b + xv.w;
    ((float4*)out)[i] = r;
}

// ---------------------------------------------------------------------------
extern "C" void kernel_launch(void* const* d_in, const int* in_sizes, int n_in,
                              void* d_out, int out_size) {
    const float* x     = (const float*)d_in[0];
    const float* wts   = (const float*)d_in[1];
    const float* gamma = (const float*)d_in[2];
    const float* beta  = (const float*)d_in[3];
    float* out = (float*)d_out;

    k0_prep<<<1, NW>>>(wts);
    k1_pack<<<PIX / 256, 256>>>(x);
    k2_conv<<<PIX / 256, 256>>>();
    k3_final<<<1, CH>>>(gamma, beta);
    k4_epilogue<<<ELEMS / 4 / 256, 256>>>(x, out);
}

// round 3
// speedup vs baseline: 1.3130x; 1.3130x over previous
#include <cuda_runtime.h>
#include <cstdint>

// Problem constants
#define NB   32
#define CH   64
#define HH   112
#define WW   112
#define HWSZ (HH*WW)             // 12544
#define PIX  (NB*HWSZ)           // 401408
#define ELEMS (NB*CH*HWSZ)       // 25690112
#define NW   576                 // 64 oc * 9 taps
#define EPSV 1e-5

// Scratch (device globals only)
__device__ unsigned long long g_xbits[PIX];          // packed activation signs
__device__ unsigned long long g_wpad[CH*10];         // packed weight signs, padded 10/channel
__device__ short              g_cs[16*CH];           // border correction per pattern x channel
__device__ float              g_scale[CH];           // mean |w| per output channel
__device__ long long          g_S1[CH];              // exact sum of s
__device__ long long          g_S2[CH];              // exact sum of s^2
__device__ short              g_sint[ELEMS];         // conv integer results (NCHW)

// ---------------------------------------------------------------------------
// K0: weight prep. 1 block, 576 threads. Packs signs (padded layout), computes
// per-channel mean|w|, zeroes stat accumulators, builds the 16-pattern border
// correction table.
// ---------------------------------------------------------------------------
__global__ void k0_prep(const float* __restrict__ wflat) {
    __shared__ float         abss[NW];
    __shared__ unsigned char wps[NW];
    int t = threadIdx.x;           // 0..575
    int o = t / 9, tap = t % 9;
    unsigned long long bits = 0ull;
    float asum = 0.0f;
    #pragma unroll 8
    for (int i = 0; i < CH; i++) {
        float w = wflat[(o * CH + i) * 9 + tap];
        bits |= (unsigned long long)(__float_as_uint(w) >> 31) << i;
        asum += fabsf(w);
    }
    g_wpad[o * 10 + tap] = bits;
    wps[t]  = (unsigned char)__popcll(bits);
    abss[t] = asum;
    __syncthreads();
    if (t < CH) {
        float s = 0.0f;
        #pragma unroll
        for (int j = 0; j < 9; j++) s += abss[t * 9 + j];
        g_scale[t] = s * (1.0f / (float)NW);
        g_S1[t] = 0ll;
        g_S2[t] = 0ll;
        g_wpad[t * 10 + 9] = 0ull;   // padding slot
    }
    // correction table: pattern bit0=top(h==0), 1=bottom, 2=left(w==0), 3=right
    for (int idx = t; idx < 16 * CH; idx += NW) {
        int p = idx >> 6, o2 = idx & 63;
        unsigned m = 0;
        if (p & 1) m |= 0x007;   // taps 0,1,2
        if (p & 2) m |= 0x1C0;   // taps 6,7,8
        if (p & 4) m |= 0x049;   // taps 0,3,6
        if (p & 8) m |= 0x124;   // taps 2,5,8
        int c = 0;
        while (m) { int tt = __ffs(m) - 1; m &= m - 1; c += wps[o2 * 9 + tt]; }
        g_cs[idx] = (short)c;
    }
}

// ---------------------------------------------------------------------------
// K1: pack sign bits of x. 4 pixels per thread, float4 loads per channel.
// ---------------------------------------------------------------------------
__global__ void __launch_bounds__(256) k1_pack(const float* __restrict__ x) {
    int t  = blockIdx.x * 256 + threadIdx.x;       // PIX/4 threads exactly
    int pb = t * 4;
    int n  = pb / HWSZ;
    int hw = pb % HWSZ;                            // HWSZ%4==0 -> same n for all 4
    const float* xp = x + (size_t)n * CH * HWSZ + hw;
    unsigned long long b0 = 0, b1 = 0, b2 = 0, b3 = 0;
    #pragma unroll 8
    for (int c = 0; c < CH; c++) {
        float4 v = *(const float4*)(xp + (size_t)c * HWSZ);
        b0 |= (unsigned long long)(__float_as_uint(v.x) >> 31) << c;
        b1 |= (unsigned long long)(__float_as_uint(v.y) >> 31) << c;
        b2 |= (unsigned long long)(__float_as_uint(v.z) >> 31) << c;
        b3 |= (unsigned long long)(__float_as_uint(v.w) >> 31) << c;
    }
    ulonglong2* dst = (ulonglong2*)(g_xbits + pb);
    dst[0] = make_ulonglong2(b0, b1);
    dst[1] = make_ulonglong2(b2, b3);
}

// ---------------------------------------------------------------------------
// K2: binary conv via xor+popc. One thread per pixel, all 64 output channels.
// Branch-free border handling via pattern table. Exact integer stats.
// ---------------------------------------------------------------------------
__global__ void __launch_bounds__(256) k2_conv(void) {
    __shared__ __align__(16) unsigned long long ws[CH * 10];
    __shared__ short cs_s[16 * CH];
    __shared__ int bs1[CH], bs2[CH];

    int tid = threadIdx.x;
    #pragma unroll
    for (int j = tid; j < CH * 10; j += 256) ws[j] = g_wpad[j];
    #pragma unroll
    for (int j = tid; j < 16 * CH; j += 256) cs_s[j] = g_cs[j];
    if (tid < CH) { bs1[tid] = 0; bs2[tid] = 0; }
    __syncthreads();

    int p  = blockIdx.x * 256 + tid;               // 401408 = 1568*256
    int n  = p / HWSZ;
    int hw = p % HWSZ;
    int h  = hw / WW;
    int w  = hw % WW;

    int pat = (h == 0) | ((h == HH - 1) << 1) | ((w == 0) << 2) | ((w == WW - 1) << 3);

    unsigned long long xb[9];
    const unsigned long long* xrow = g_xbits + (size_t)n * HWSZ;
    #pragma unroll
    for (int dh = -1; dh <= 1; dh++) {
        #pragma unroll
        for (int dw = -1; dw <= 1; dw++) {
            int t2 = (dh + 1) * 3 + (dw + 1);
            int hh = h + dh, w2 = w + dw;
            bool valid = (hh >= 0) & (hh < HH) & (w2 >= 0) & (w2 < WW);
            xb[t2] = valid ? xrow[hh * WW + w2] : 0ull;
        }
    }
    int nv64 = 64 * (9 - (!!(pat & 1) + !!(pat & 2) + !!(pat & 4) + !!(pat & 8)) * 3
                       + ((pat & 1) && (pat & 4)) + ((pat & 1) && (pat & 8))
                       + ((pat & 2) && (pat & 4)) + ((pat & 2) && (pat & 8)));
    const short* csrow = cs_s + (pat << 6);
    size_t obase = (size_t)n * CH * HWSZ + hw;
    int lane0 = ((tid & 31) == 0);

    #pragma unroll 2
    for (int o = 0; o < CH; o++) {
        const ulonglong2* wv = (const ulonglong2*)(ws + o * 10);
        ulonglong2 w01 = wv[0], w23 = wv[1], w45 = wv[2], w67 = wv[3];
        unsigned long long w8 = ws[o * 10 + 8];
        int acc = __popcll(xb[0] ^ w01.x) + __popcll(xb[1] ^ w01.y)
                + __popcll(xb[2] ^ w23.x) + __popcll(xb[3] ^ w23.y)
                + __popcll(xb[4] ^ w45.x) + __popcll(xb[5] ^ w45.y)
                + __popcll(xb[6] ^ w67.x) + __popcll(xb[7] ^ w67.y)
                + __popcll(xb[8] ^ w8);
        int s = nv64 - 2 * acc + 2 * (int)csrow[o];
        g_sint[obase + (size_t)o * HWSZ] = (short)s;

        int s1 = __reduce_add_sync(0xffffffffu, s);
        int s2 = __reduce_add_sync(0xffffffffu, s * s);
        if (lane0) { atomicAdd(&bs1[o], s1); atomicAdd(&bs2[o], s2); }
    }
    __syncthreads();
    if (tid < CH) {
        atomicAdd((unsigned long long*)&g_S1[tid], (unsigned long long)(long long)bs1[tid]);
        atomicAdd((unsigned long long*)&g_S2[tid], (unsigned long long)(long long)bs2[tid]);
    }
}

// ---------------------------------------------------------------------------
// K4: BN fold (per-block preamble, exact double) + elementwise epilogue
//     out = s*A[o] + B[o] + x,  16 float4 per thread.
// ---------------------------------------------------------------------------
__global__ void __launch_bounds__(256) k4_epilogue(
    const float* __restrict__ x, const float* __restrict__ gamma,
    const float* __restrict__ beta, float* __restrict__ out)
{
    __shared__ float sA[CH], sB[CH];
    int tid = threadIdx.x;
    if (tid < CH) {
        const double cnt = (double)PIX;
        double sc   = (double)g_scale[tid];
        double mean = sc * ((double)g_S1[tid] / cnt);
        double ex2  = sc * sc * ((double)g_S2[tid] / cnt);
        double var  = ex2 - mean * mean;
        double inv  = (double)gamma[tid] * rsqrt(var + EPSV);
        sA[tid] = (float)(sc * inv);
        sB[tid] = (float)((double)beta[tid] - mean * inv);
    }
    __syncthreads();

    int base = blockIdx.x * 4096;                  // ELEMS/4 = 6422528 = 1568*4096
    #pragma unroll 4
    for (int it = 0; it < 16; it++) {
        int i = base + it * 256 + tid;
        int o = (i / (HWSZ / 4)) & (CH - 1);
        float a = sA[o], b = sB[o];
        float4 xv = ((const float4*)x)[i];
        short4 sv = ((const short4*)g_sint)[i];
        float4 r;
        r.x = fmaf((float)sv.x, a, b) + xv.x;
        r.y = fmaf((float)sv.y, a, b) + xv.y;
        r.z = fmaf((float)sv.z, a, b) + xv.z;
        r.w = fmaf((float)sv.w, a, b) + xv.w;
        ((float4*)out)[i] = r;
    }
}

// ---------------------------------------------------------------------------
extern "C" void kernel_launch(void* const* d_in, const int* in_sizes, int n_in,
                              void* d_out, int out_size) {
    const float* x     = (const float*)d_in[0];
    const float* wts   = (const float*)d_in[1];
    const float* gamma = (const float*)d_in[2];
    const float* beta  = (const float*)d_in[3];
    float* out = (float*)d_out;

    k0_prep<<<1, NW>>>(wts);
    k1_pack<<<PIX / 4 / 256, 256>>>(x);
    k2_conv<<<PIX / 256, 256>>>();
    k4_epilogue<<<1568, 256>>>(x, gamma, beta, out);
}